// round 1
// baseline (speedup 1.0000x reference)
#include <cuda_runtime.h>

#define TR 64
#define NT 256

// ---- device scratch (allocation-free rule: __device__ globals) ----
__device__ float g_nh[50000 * 128];
__device__ float g_eh[500000 * 128];
__device__ float g_rc[50000 * 128];

__device__ __forceinline__ float gelu_f(float x) {
    // jax.nn.gelu default (approximate=True, tanh form)
    float t = tanhf(0.7978845608028654f * (x + 0.044715f * x * x * x));
    return 0.5f * x * (1.0f + t);
}

__device__ __forceinline__ float wred(float v) {
#pragma unroll
    for (int o = 16; o; o >>= 1) v += __shfl_xor_sync(0xffffffffu, v, o);
    return v;
}

// MODE 0: plain embed (in0 [nrows,K] -> out [nrows,128])
// MODE 1: edge step  (gather [eh, nh[snd], nh[rcv], g] -> new_e; atomic recv; optional LN->eh)
// MODE 2: node step  (gather [nh, recv, g] -> new_n; LN->nh)
// MODE 3: decode     (nh -> hidden gelu -> out [nrows,3])
template <int K, int KPAD, int MODE>
__global__ void __launch_bounds__(NT) mlp_k(
    int nrows,
    const float* __restrict__ in0,
    const float* __restrict__ W0, const float* __restrict__ b0,
    const float* __restrict__ W1, const float* __restrict__ b1,
    float* __restrict__ outp,
    const int* __restrict__ snd, const int* __restrict__ rcv,
    const float* __restrict__ nhp, const float* __restrict__ ehp,
    const float* __restrict__ glob,
    float* __restrict__ rca,
    const float* __restrict__ lnsc, const float* __restrict__ lnbs,
    int write_ln)
{
    extern __shared__ float sm[];
    float* in_t = sm;                // [TR][KPAD]
    float* hid  = sm + TR * KPAD;    // [TR][128]
    __shared__ int snd_sh[TR], rcv_sh[TR];

    const int tid  = threadIdx.x;
    const int lane = tid & 31;
    const int wrp  = tid >> 5;
    const int row0 = blockIdx.x * TR;

    if constexpr (MODE == 1) {
        if (tid < TR) {
            int row = row0 + tid;
            snd_sh[tid] = (row < nrows) ? snd[row] : 0;
        } else if (tid < 2 * TR) {
            int r = tid - TR; int row = row0 + r;
            rcv_sh[r] = (row < nrows) ? rcv[row] : 0;
        }
        __syncthreads();
    }

    // ---- gather A tile ----
    if constexpr (MODE == 0) {
        for (int i = tid; i < TR * K; i += NT) {
            int r = i / K, k = i - r * K;
            int row = row0 + r;
            in_t[r * KPAD + k] = (row < nrows) ? in0[(size_t)row * K + k] : 0.f;
        }
    } else if constexpr (MODE == 1) {
        const int QP = 97;  // 97 float4 per row (388 floats)
        float g0 = glob[0], g1 = glob[1];
        for (int i = tid; i < TR * QP; i += NT) {
            int r = i / QP, q = i - r * QP;
            int row = row0 + r;
            float4 v = make_float4(0.f, 0.f, 0.f, 0.f);
            if (row < nrows) {
                if (q < 32)      v = ((const float4*)(ehp + (size_t)row * 128))[q];
                else if (q < 64) v = ((const float4*)(nhp + (size_t)snd_sh[r] * 128))[q - 32];
                else if (q < 96) v = ((const float4*)(nhp + (size_t)rcv_sh[r] * 128))[q - 64];
                else { v.x = g0; v.y = g1; }
            }
            ((float4*)(in_t + r * KPAD))[q] = v;
        }
    } else if constexpr (MODE == 2) {
        const int QP = 65;  // 65 float4 per row (260 floats)
        float g0 = glob[0], g1 = glob[1];
        for (int i = tid; i < TR * QP; i += NT) {
            int r = i / QP, q = i - r * QP;
            int row = row0 + r;
            float4 v = make_float4(0.f, 0.f, 0.f, 0.f);
            if (row < nrows) {
                if (q < 32)      v = ((const float4*)(nhp + (size_t)row * 128))[q];
                else if (q < 64) v = ((const float4*)(rca + (size_t)row * 128))[q - 32];
                else { v.x = g0; v.y = g1; }
            }
            ((float4*)(in_t + r * KPAD))[q] = v;
        }
    } else {  // MODE 3: K = 128 from nh
        for (int i = tid; i < TR * 32; i += NT) {
            int r = i >> 5, q = i & 31;
            int row = row0 + r;
            float4 v = (row < nrows) ? ((const float4*)(nhp + (size_t)row * 128))[q]
                                     : make_float4(0.f, 0.f, 0.f, 0.f);
            ((float4*)(in_t + r * KPAD))[q] = v;
        }
    }
    __syncthreads();

    // ---- layer 1: [TR,K] @ [K,128] + b0, gelu -> hid ----
    float acc[8][4];
    {
        float4 bv = ((const float4*)b0)[lane];
#pragma unroll
        for (int i = 0; i < 8; i++) {
            acc[i][0] = bv.x; acc[i][1] = bv.y; acc[i][2] = bv.z; acc[i][3] = bv.w;
        }
    }
    const float4* W0v = (const float4*)W0;
    const float* arow = in_t + (wrp * 8) * KPAD;
#pragma unroll 2
    for (int k = 0; k < K; k++) {
        float4 w = __ldg(&W0v[k * 32 + lane]);
#pragma unroll
        for (int i = 0; i < 8; i++) {
            float a = arow[i * KPAD + k];
            acc[i][0] += a * w.x; acc[i][1] += a * w.y;
            acc[i][2] += a * w.z; acc[i][3] += a * w.w;
        }
    }
#pragma unroll
    for (int i = 0; i < 8; i++) {
        float4 h;
        h.x = gelu_f(acc[i][0]); h.y = gelu_f(acc[i][1]);
        h.z = gelu_f(acc[i][2]); h.w = gelu_f(acc[i][3]);
        ((float4*)(hid + (wrp * 8 + i) * 128))[lane] = h;
    }
    __syncthreads();

    if constexpr (MODE == 3) {
        // small decode layer-2: hid[TR,128] @ W1[128,3] + b1
        if (tid < TR * 3) {
            int r = tid / 3, c = tid - r * 3;
            float s = b1[c];
            const float* hr = hid + r * 128;
#pragma unroll 4
            for (int kk = 0; kk < 128; kk++) {
                int k = (kk + r) & 127;  // bank rotation
                s += hr[k] * W1[k * 3 + c];
            }
            int row = row0 + r;
            if (row < nrows) outp[(size_t)row * 3 + c] = s;
        }
        return;
    }

    // ---- layer 2: hid[TR,128] @ [128,128] + b1 ----
    float a2[8][4];
    {
        float4 bv = ((const float4*)b1)[lane];
#pragma unroll
        for (int i = 0; i < 8; i++) {
            a2[i][0] = bv.x; a2[i][1] = bv.y; a2[i][2] = bv.z; a2[i][3] = bv.w;
        }
    }
    const float4* W1v = (const float4*)W1;
    const float* hrow = hid + (wrp * 8) * 128;
#pragma unroll 2
    for (int k = 0; k < 128; k++) {
        float4 w = __ldg(&W1v[k * 32 + lane]);
#pragma unroll
        for (int i = 0; i < 8; i++) {
            float a = hrow[i * 128 + k];
            a2[i][0] += a * w.x; a2[i][1] += a * w.y;
            a2[i][2] += a * w.z; a2[i][3] += a * w.w;
        }
    }

    if constexpr (MODE == 0) {
#pragma unroll
        for (int i = 0; i < 8; i++) {
            int row = row0 + wrp * 8 + i;
            if (row < nrows) {
                float4 o = make_float4(a2[i][0], a2[i][1], a2[i][2], a2[i][3]);
                ((float4*)(outp + (size_t)row * 128))[lane] = o;
            }
        }
        return;
    }

    // ---- step epilogue: atomic segment-sum (edge) + skip + LayerNorm ----
#pragma unroll
    for (int i = 0; i < 8; i++) {
        int r = wrp * 8 + i;
        int row = row0 + r;
        if (row < nrows) {
            if constexpr (MODE == 1) {
                float* dst = rca + (size_t)rcv_sh[r] * 128 + 4 * lane;
                atomicAdd(dst + 0, a2[i][0]); atomicAdd(dst + 1, a2[i][1]);
                atomicAdd(dst + 2, a2[i][2]); atomicAdd(dst + 3, a2[i][3]);
            }
            if (write_ln) {
                // in_t[r][0:128] still holds the old eh/nh row (skip input)
                float* st = in_t + r * KPAD + 4 * lane;
                st[0] += a2[i][0]; st[1] += a2[i][1];
                st[2] += a2[i][2]; st[3] += a2[i][3];
            }
        }
    }
    if (write_ln) {
        __syncthreads();
        float4 sc = ((const float4*)lnsc)[lane];
        float4 bs = ((const float4*)lnbs)[lane];
        for (int r = wrp; r < TR; r += 8) {
            int row = row0 + r;
            float4 x = ((float4*)(in_t + r * KPAD))[lane];
            float s = wred(x.x + x.y + x.z + x.w);
            float mean = s * (1.f / 128.f);
            float dx = x.x - mean, dy = x.y - mean, dz = x.z - mean, dw = x.w - mean;
            float v = wred(dx * dx + dy * dy + dz * dz + dw * dw);
            float inv = rsqrtf(v * (1.f / 128.f) + 1e-6f);
            if (row < nrows) {
                float4 o;
                o.x = dx * inv * sc.x + bs.x; o.y = dy * inv * sc.y + bs.y;
                o.z = dz * inv * sc.z + bs.z; o.w = dw * inv * sc.w + bs.w;
                ((float4*)(outp + (size_t)row * 128))[lane] = o;
            }
        }
    }
}

__global__ void zerok(float4* p, int n4) {
    int i = blockIdx.x * blockDim.x + threadIdx.x;
    if (i < n4) p[i] = make_float4(0.f, 0.f, 0.f, 0.f);
}

extern "C" void kernel_launch(void* const* d_in, const int* in_sizes, int n_in,
                              void* d_out, int out_size)
{
    const float* nodes  = (const float*)d_in[0];
    const float* edges  = (const float*)d_in[1];
    const float* glob   = (const float*)d_in[2];
    const int*   snd    = (const int*)d_in[3];
    const int*   rcv    = (const int*)d_in[4];
    const float* ne_W0  = (const float*)d_in[5];
    const float* ne_b0  = (const float*)d_in[6];
    const float* ne_W1  = (const float*)d_in[7];
    const float* ne_b1  = (const float*)d_in[8];
    const float* ee_W0  = (const float*)d_in[9];
    const float* ee_b0  = (const float*)d_in[10];
    const float* ee_W1  = (const float*)d_in[11];
    const float* ee_b1  = (const float*)d_in[12];
    const float* eu_W0  = (const float*)d_in[13];
    const float* eu_b0  = (const float*)d_in[14];
    const float* eu_W1  = (const float*)d_in[15];
    const float* eu_b1  = (const float*)d_in[16];
    const float* nu_W0  = (const float*)d_in[17];
    const float* nu_b0  = (const float*)d_in[18];
    const float* nu_W1  = (const float*)d_in[19];
    const float* nu_b1  = (const float*)d_in[20];
    const float* lnsc   = (const float*)d_in[21];
    const float* lnbs   = (const float*)d_in[22];
    const float* dec_W0 = (const float*)d_in[23];
    const float* dec_b0 = (const float*)d_in[24];
    const float* dec_W1 = (const float*)d_in[25];
    const float* dec_b1 = (const float*)d_in[26];
    float* out = (float*)d_out;

    const int N = in_sizes[0] / 7;
    const int E = in_sizes[1] / 3;

    float *nh, *eh, *rc;
    cudaGetSymbolAddress((void**)&nh, g_nh);
    cudaGetSymbolAddress((void**)&eh, g_eh);
    cudaGetSymbolAddress((void**)&rc, g_rc);

    const int SM_EMB_N = (TR * 8 + TR * 128) * 4;     // 34816
    const int SM_EMB_E = (TR * 4 + TR * 128) * 4;     // 33792
    const int SM_EDGE  = (TR * 388 + TR * 128) * 4;   // 132096
    const int SM_NODE  = (TR * 260 + TR * 128) * 4;   // 99328
    const int SM_DEC   = (TR * 128 + TR * 128) * 4;   // 65536

    cudaFuncSetAttribute(mlp_k<386, 388, 1>, cudaFuncAttributeMaxDynamicSharedMemorySize, SM_EDGE);
    cudaFuncSetAttribute(mlp_k<258, 260, 2>, cudaFuncAttributeMaxDynamicSharedMemorySize, SM_NODE);
    cudaFuncSetAttribute(mlp_k<128, 128, 3>, cudaFuncAttributeMaxDynamicSharedMemorySize, SM_DEC);

    const int nbN = (N + TR - 1) / TR;
    const int nbE = (E + TR - 1) / TR;

    // embed
    mlp_k<7, 8, 0><<<nbN, NT, SM_EMB_N>>>(N, nodes, ne_W0, ne_b0, ne_W1, ne_b1, nh,
        nullptr, nullptr, nullptr, nullptr, nullptr, nullptr, nullptr, nullptr, 0);
    mlp_k<3, 4, 0><<<nbE, NT, SM_EMB_E>>>(E, edges, ee_W0, ee_b0, ee_W1, ee_b1, eh,
        nullptr, nullptr, nullptr, nullptr, nullptr, nullptr, nullptr, nullptr, 0);

    for (int s = 0; s < 2; s++) {
        int n4 = N * 32;
        zerok<<<(n4 + 255) / 256, 256>>>((float4*)rc, n4);
        mlp_k<386, 388, 1><<<nbE, NT, SM_EDGE>>>(E, nullptr,
            eu_W0 + (size_t)s * 386 * 128, eu_b0 + s * 128,
            eu_W1 + (size_t)s * 128 * 128, eu_b1 + s * 128,
            eh, snd, rcv, nh, eh, glob, rc, lnsc, lnbs, (s == 0) ? 1 : 0);
        mlp_k<258, 260, 2><<<nbN, NT, SM_NODE>>>(N, nullptr,
            nu_W0 + (size_t)s * 258 * 128, nu_b0 + s * 128,
            nu_W1 + (size_t)s * 128 * 128, nu_b1 + s * 128,
            nh, nullptr, nullptr, nh, nullptr, glob, rc, lnsc, lnbs, 1);
    }

    // decode
    mlp_k<128, 128, 3><<<nbN, NT, SM_DEC>>>(N, nullptr,
        dec_W0, dec_b0, dec_W1, dec_b1, out,
        nullptr, nullptr, nh, nullptr, nullptr, nullptr, nullptr, nullptr, 0);
}

// round 2
// speedup vs baseline: 1.0000x; 1.0000x over previous
#include <cuda_runtime.h>

#define TR 64
#define NT 256

// ---- device scratch (allocation-free rule: __device__ globals) ----
__device__ float g_nh[50000 * 128];
__device__ float g_eh[500000 * 128];
__device__ float g_rc[50000 * 128];

__device__ __forceinline__ float gelu_f(float x) {
    // jax.nn.gelu default (approximate=True, tanh form)
    float t = tanhf(0.7978845608028654f * (x + 0.044715f * x * x * x));
    return 0.5f * x * (1.0f + t);
}

__device__ __forceinline__ float wred(float v) {
#pragma unroll
    for (int o = 16; o; o >>= 1) v += __shfl_xor_sync(0xffffffffu, v, o);
    return v;
}

// MODE 0: plain embed (in0 [nrows,K] -> out [nrows,128])
// MODE 1: edge step  (gather [eh, nh[snd], nh[rcv], g] -> new_e; atomic recv; optional LN->eh)
// MODE 2: node step  (gather [nh, recv, g] -> new_n; LN->nh)
// MODE 3: decode     (nh -> hidden gelu -> out [nrows,3])
template <int K, int KPAD, int MODE>
__global__ void __launch_bounds__(NT) mlp_k(
    int nrows,
    const float* __restrict__ in0,
    const float* __restrict__ W0, const float* __restrict__ b0,
    const float* __restrict__ W1, const float* __restrict__ b1,
    float* __restrict__ outp,
    const int* __restrict__ snd, const int* __restrict__ rcv,
    const float* __restrict__ nhp, const float* __restrict__ ehp,
    const float* __restrict__ glob,
    float* __restrict__ rca,
    const float* __restrict__ lnsc, const float* __restrict__ lnbs,
    int write_ln)
{
    extern __shared__ float sm[];
    float* in_t = sm;                // [TR][KPAD]
    float* hid  = sm + TR * KPAD;    // [TR][128]
    __shared__ int snd_sh[TR], rcv_sh[TR];

    const int tid  = threadIdx.x;
    const int lane = tid & 31;
    const int wrp  = tid >> 5;
    const int row0 = blockIdx.x * TR;

    if constexpr (MODE == 1) {
        if (tid < TR) {
            int row = row0 + tid;
            snd_sh[tid] = (row < nrows) ? snd[row] : 0;
        } else if (tid < 2 * TR) {
            int r = tid - TR; int row = row0 + r;
            rcv_sh[r] = (row < nrows) ? rcv[row] : 0;
        }
        __syncthreads();
    }

    // ---- gather A tile ----
    if constexpr (MODE == 0) {
        for (int i = tid; i < TR * K; i += NT) {
            int r = i / K, k = i - r * K;
            int row = row0 + r;
            in_t[r * KPAD + k] = (row < nrows) ? in0[(size_t)row * K + k] : 0.f;
        }
    } else if constexpr (MODE == 1) {
        const int QP = 97;  // 97 float4 per row (388 floats)
        float g0 = glob[0], g1 = glob[1];
        for (int i = tid; i < TR * QP; i += NT) {
            int r = i / QP, q = i - r * QP;
            int row = row0 + r;
            float4 v = make_float4(0.f, 0.f, 0.f, 0.f);
            if (row < nrows) {
                if (q < 32)      v = ((const float4*)(ehp + (size_t)row * 128))[q];
                else if (q < 64) v = ((const float4*)(nhp + (size_t)snd_sh[r] * 128))[q - 32];
                else if (q < 96) v = ((const float4*)(nhp + (size_t)rcv_sh[r] * 128))[q - 64];
                else { v.x = g0; v.y = g1; }
            }
            ((float4*)(in_t + r * KPAD))[q] = v;
        }
    } else if constexpr (MODE == 2) {
        const int QP = 65;  // 65 float4 per row (260 floats)
        float g0 = glob[0], g1 = glob[1];
        for (int i = tid; i < TR * QP; i += NT) {
            int r = i / QP, q = i - r * QP;
            int row = row0 + r;
            float4 v = make_float4(0.f, 0.f, 0.f, 0.f);
            if (row < nrows) {
                if (q < 32)      v = ((const float4*)(nhp + (size_t)row * 128))[q];
                else if (q < 64) v = ((const float4*)(rca + (size_t)row * 128))[q - 32];
                else { v.x = g0; v.y = g1; }
            }
            ((float4*)(in_t + r * KPAD))[q] = v;
        }
    } else {  // MODE 3: K = 128 from nh
        for (int i = tid; i < TR * 32; i += NT) {
            int r = i >> 5, q = i & 31;
            int row = row0 + r;
            float4 v = (row < nrows) ? ((const float4*)(nhp + (size_t)row * 128))[q]
                                     : make_float4(0.f, 0.f, 0.f, 0.f);
            ((float4*)(in_t + r * KPAD))[q] = v;
        }
    }
    __syncthreads();

    // ---- layer 1: [TR,K] @ [K,128] + b0, gelu -> hid ----
    float acc[8][4];
    {
        float4 bv = ((const float4*)b0)[lane];
#pragma unroll
        for (int i = 0; i < 8; i++) {
            acc[i][0] = bv.x; acc[i][1] = bv.y; acc[i][2] = bv.z; acc[i][3] = bv.w;
        }
    }
    const float4* W0v = (const float4*)W0;
    const float* arow = in_t + (wrp * 8) * KPAD;
#pragma unroll 2
    for (int k = 0; k < K; k++) {
        float4 w = __ldg(&W0v[k * 32 + lane]);
#pragma unroll
        for (int i = 0; i < 8; i++) {
            float a = arow[i * KPAD + k];
            acc[i][0] += a * w.x; acc[i][1] += a * w.y;
            acc[i][2] += a * w.z; acc[i][3] += a * w.w;
        }
    }
#pragma unroll
    for (int i = 0; i < 8; i++) {
        float4 h;
        h.x = gelu_f(acc[i][0]); h.y = gelu_f(acc[i][1]);
        h.z = gelu_f(acc[i][2]); h.w = gelu_f(acc[i][3]);
        ((float4*)(hid + (wrp * 8 + i) * 128))[lane] = h;
    }
    __syncthreads();

    if constexpr (MODE == 3) {
        // small decode layer-2: hid[TR,128] @ W1[128,3] + b1
        if (tid < TR * 3) {
            int r = tid / 3, c = tid - r * 3;
            float s = b1[c];
            const float* hr = hid + r * 128;
#pragma unroll 4
            for (int kk = 0; kk < 128; kk++) {
                int k = (kk + r) & 127;  // bank rotation
                s += hr[k] * W1[k * 3 + c];
            }
            int row = row0 + r;
            if (row < nrows) outp[(size_t)row * 3 + c] = s;
        }
        return;
    }

    // ---- layer 2: hid[TR,128] @ [128,128] + b1 ----
    float a2[8][4];
    {
        float4 bv = ((const float4*)b1)[lane];
#pragma unroll
        for (int i = 0; i < 8; i++) {
            a2[i][0] = bv.x; a2[i][1] = bv.y; a2[i][2] = bv.z; a2[i][3] = bv.w;
        }
    }
    const float4* W1v = (const float4*)W1;
    const float* hrow = hid + (wrp * 8) * 128;
#pragma unroll 2
    for (int k = 0; k < 128; k++) {
        float4 w = __ldg(&W1v[k * 32 + lane]);
#pragma unroll
        for (int i = 0; i < 8; i++) {
            float a = hrow[i * 128 + k];
            a2[i][0] += a * w.x; a2[i][1] += a * w.y;
            a2[i][2] += a * w.z; a2[i][3] += a * w.w;
        }
    }

    if constexpr (MODE == 0) {
#pragma unroll
        for (int i = 0; i < 8; i++) {
            int row = row0 + wrp * 8 + i;
            if (row < nrows) {
                float4 o = make_float4(a2[i][0], a2[i][1], a2[i][2], a2[i][3]);
                ((float4*)(outp + (size_t)row * 128))[lane] = o;
            }
        }
        return;
    }

    // ---- step epilogue: atomic segment-sum (edge) + skip + LayerNorm ----
#pragma unroll
    for (int i = 0; i < 8; i++) {
        int r = wrp * 8 + i;
        int row = row0 + r;
        if (row < nrows) {
            if constexpr (MODE == 1) {
                float* dst = rca + (size_t)rcv_sh[r] * 128 + 4 * lane;
                atomicAdd(dst + 0, a2[i][0]); atomicAdd(dst + 1, a2[i][1]);
                atomicAdd(dst + 2, a2[i][2]); atomicAdd(dst + 3, a2[i][3]);
            }
            if (write_ln) {
                // in_t[r][0:128] still holds the old eh/nh row (skip input)
                float* st = in_t + r * KPAD + 4 * lane;
                st[0] += a2[i][0]; st[1] += a2[i][1];
                st[2] += a2[i][2]; st[3] += a2[i][3];
            }
        }
    }
    if (write_ln) {
        __syncthreads();
        float4 sc = ((const float4*)lnsc)[lane];
        float4 bs = ((const float4*)lnbs)[lane];
        for (int r = wrp; r < TR; r += 8) {
            int row = row0 + r;
            float4 x = ((float4*)(in_t + r * KPAD))[lane];
            float s = wred(x.x + x.y + x.z + x.w);
            float mean = s * (1.f / 128.f);
            float dx = x.x - mean, dy = x.y - mean, dz = x.z - mean, dw = x.w - mean;
            float v = wred(dx * dx + dy * dy + dz * dz + dw * dw);
            float inv = rsqrtf(v * (1.f / 128.f) + 1e-6f);
            if (row < nrows) {
                float4 o;
                o.x = dx * inv * sc.x + bs.x; o.y = dy * inv * sc.y + bs.y;
                o.z = dz * inv * sc.z + bs.z; o.w = dw * inv * sc.w + bs.w;
                ((float4*)(outp + (size_t)row * 128))[lane] = o;
            }
        }
    }
}

__global__ void zerok(float4* p, int n4) {
    int i = blockIdx.x * blockDim.x + threadIdx.x;
    if (i < n4) p[i] = make_float4(0.f, 0.f, 0.f, 0.f);
}

extern "C" void kernel_launch(void* const* d_in, const int* in_sizes, int n_in,
                              void* d_out, int out_size)
{
    const float* nodes  = (const float*)d_in[0];
    const float* edges  = (const float*)d_in[1];
    const float* glob   = (const float*)d_in[2];
    const int*   snd    = (const int*)d_in[3];
    const int*   rcv    = (const int*)d_in[4];
    const float* ne_W0  = (const float*)d_in[5];
    const float* ne_b0  = (const float*)d_in[6];
    const float* ne_W1  = (const float*)d_in[7];
    const float* ne_b1  = (const float*)d_in[8];
    const float* ee_W0  = (const float*)d_in[9];
    const float* ee_b0  = (const float*)d_in[10];
    const float* ee_W1  = (const float*)d_in[11];
    const float* ee_b1  = (const float*)d_in[12];
    const float* eu_W0  = (const float*)d_in[13];
    const float* eu_b0  = (const float*)d_in[14];
    const float* eu_W1  = (const float*)d_in[15];
    const float* eu_b1  = (const float*)d_in[16];
    const float* nu_W0  = (const float*)d_in[17];
    const float* nu_b0  = (const float*)d_in[18];
    const float* nu_W1  = (const float*)d_in[19];
    const float* nu_b1  = (const float*)d_in[20];
    const float* lnsc   = (const float*)d_in[21];
    const float* lnbs   = (const float*)d_in[22];
    const float* dec_W0 = (const float*)d_in[23];
    const float* dec_b0 = (const float*)d_in[24];
    const float* dec_W1 = (const float*)d_in[25];
    const float* dec_b1 = (const float*)d_in[26];
    float* out = (float*)d_out;

    const int N = in_sizes[0] / 7;
    const int E = in_sizes[1] / 3;

    float *nh, *eh, *rc;
    cudaGetSymbolAddress((void**)&nh, g_nh);
    cudaGetSymbolAddress((void**)&eh, g_eh);
    cudaGetSymbolAddress((void**)&rc, g_rc);

    const int SM_EMB_N = (TR * 8 + TR * 128) * 4;     // 34816
    const int SM_EMB_E = (TR * 4 + TR * 128) * 4;     // 33792
    const int SM_EDGE  = (TR * 388 + TR * 128) * 4;   // 132096
    const int SM_NODE  = (TR * 260 + TR * 128) * 4;   // 99328
    const int SM_DEC   = (TR * 128 + TR * 128) * 4;   // 65536

    cudaFuncSetAttribute(mlp_k<386, 388, 1>, cudaFuncAttributeMaxDynamicSharedMemorySize, SM_EDGE);
    cudaFuncSetAttribute(mlp_k<258, 260, 2>, cudaFuncAttributeMaxDynamicSharedMemorySize, SM_NODE);
    cudaFuncSetAttribute(mlp_k<128, 128, 3>, cudaFuncAttributeMaxDynamicSharedMemorySize, SM_DEC);

    const int nbN = (N + TR - 1) / TR;
    const int nbE = (E + TR - 1) / TR;

    // embed
    mlp_k<7, 8, 0><<<nbN, NT, SM_EMB_N>>>(N, nodes, ne_W0, ne_b0, ne_W1, ne_b1, nh,
        nullptr, nullptr, nullptr, nullptr, nullptr, nullptr, nullptr, nullptr, 0);
    mlp_k<3, 4, 0><<<nbE, NT, SM_EMB_E>>>(E, edges, ee_W0, ee_b0, ee_W1, ee_b1, eh,
        nullptr, nullptr, nullptr, nullptr, nullptr, nullptr, nullptr, nullptr, 0);

    for (int s = 0; s < 2; s++) {
        int n4 = N * 32;
        zerok<<<(n4 + 255) / 256, 256>>>((float4*)rc, n4);
        mlp_k<386, 388, 1><<<nbE, NT, SM_EDGE>>>(E, nullptr,
            eu_W0 + (size_t)s * 386 * 128, eu_b0 + s * 128,
            eu_W1 + (size_t)s * 128 * 128, eu_b1 + s * 128,
            eh, snd, rcv, nh, eh, glob, rc, lnsc, lnbs, (s == 0) ? 1 : 0);
        mlp_k<258, 260, 2><<<nbN, NT, SM_NODE>>>(N, nullptr,
            nu_W0 + (size_t)s * 258 * 128, nu_b0 + s * 128,
            nu_W1 + (size_t)s * 128 * 128, nu_b1 + s * 128,
            nh, nullptr, nullptr, nh, nullptr, glob, rc, lnsc, lnbs, 1);
    }

    // decode
    mlp_k<128, 128, 3><<<nbN, NT, SM_DEC>>>(N, nullptr,
        dec_W0, dec_b0, dec_W1, dec_b1, out,
        nullptr, nullptr, nh, nullptr, nullptr, nullptr, nullptr, nullptr, 0);
}

// round 4
// speedup vs baseline: 3.7769x; 3.7767x over previous
#include <cuda_runtime.h>
#include <cuda_bf16.h>
#include <stdint.h>

#define NT 256

__device__ float g_nh[50000 * 128];
__device__ float g_eh[500000 * 128];
__device__ float g_rc[50000 * 128];
__device__ __nv_bfloat16 g_whi[327680];
__device__ __nv_bfloat16 g_wlo[327680];

static __device__ __forceinline__ float gelu_f(float x) {
    float t = tanhf(0.7978845608028654f * (x + 0.044715f * x * x * x));
    return 0.5f * x * (1.0f + t);
}
static __device__ __forceinline__ float wred(float v) {
#pragma unroll
    for (int o = 16; o; o >>= 1) v += __shfl_xor_sync(0xffffffffu, v, o);
    return v;
}
static __device__ __forceinline__ uint32_t packh(float x, float y) {
    __nv_bfloat162 h; h.x = __float2bfloat16(x); h.y = __float2bfloat16(y);
    return *(uint32_t*)&h;
}
static __device__ __forceinline__ uint32_t packl(float x, float y, uint32_t hw) {
    __nv_bfloat162 hh = *(__nv_bfloat162*)&hw;
    __nv_bfloat162 l;
    l.x = __float2bfloat16(x - __bfloat162float(hh.x));
    l.y = __float2bfloat16(y - __bfloat162float(hh.y));
    return *(uint32_t*)&l;
}
static __device__ __forceinline__ void mmabf(float* d, const uint32_t* a, const uint32_t* b) {
    asm volatile(
        "mma.sync.aligned.m16n8k16.row.col.f32.bf16.bf16.f32 "
        "{%0,%1,%2,%3}, {%4,%5,%6,%7}, {%8,%9}, {%0,%1,%2,%3};"
        : "+f"(d[0]), "+f"(d[1]), "+f"(d[2]), "+f"(d[3])
        : "r"(a[0]), "r"(a[1]), "r"(a[2]), "r"(a[3]), "r"(b[0]), "r"(b[1]));
}

// transpose W[K,128] -> [n][Kpad] bf16 hi/lo
__global__ void prep(const float* __restrict__ W, int K, int Kpad, int off) {
    int idx = blockIdx.x * NT + threadIdx.x;
    if (idx >= Kpad * 128) return;
    int k = idx >> 7, n = idx & 127;
    float x = (k < K) ? W[k * 128 + n] : 0.f;
    __nv_bfloat16 h = __float2bfloat16(x);
    __nv_bfloat16 l = __float2bfloat16(x - __bfloat162float(h));
    g_whi[off + n * Kpad + k] = h;
    g_wlo[off + n * Kpad + k] = l;
}

__global__ void zerok(float4* p, int n4) {
    int i = blockIdx.x * blockDim.x + threadIdx.x;
    if (i < n4) p[i] = make_float4(0.f, 0.f, 0.f, 0.f);
}

// smem layout (bytes), dynamic base dsm:
//   GEMM1:  sAh 0..18432  sAl 18432..36864   (128 x 72 halves each)
//   A2:     sA2h 0..34816 sA2l 34816..69632  (128 x 136 halves each)
//   B:      sBh 69632..88064  sBl 88064..106496 (128 x 72 halves each)
//   sD:     float[128][132] 0..67584 (post-GEMM2 / MODE3 post-GEMM1)
#define SMEMSZ 106496

// MODE 0: embed  1: edge step  2: node step  3: decode (in0 = dec_W1 [128,3])
template <int MODE, int NC, int KIN>
__global__ void __launch_bounds__(NT) gk(
    int nrows, const float* __restrict__ in0, int w0off, int w1off,
    const float* __restrict__ b0, const float* __restrict__ b1,
    float* __restrict__ outp,
    const int* __restrict__ snd, const int* __restrict__ rcv,
    const float* __restrict__ nhp, const float* __restrict__ ehp,
    const float* __restrict__ glob, float* __restrict__ rca,
    const float* __restrict__ lnsc, const float* __restrict__ lnbs, int write_ln)
{
    extern __shared__ char dsm[];
    __nv_bfloat16* sAh  = (__nv_bfloat16*)dsm;
    __nv_bfloat16* sAl  = (__nv_bfloat16*)(dsm + 18432);
    __nv_bfloat16* sA2h = (__nv_bfloat16*)dsm;
    __nv_bfloat16* sA2l = (__nv_bfloat16*)(dsm + 34816);
    __nv_bfloat16* sBh  = (__nv_bfloat16*)(dsm + 69632);
    __nv_bfloat16* sBl  = (__nv_bfloat16*)(dsm + 88064);
    float* sD = (float*)dsm;
    __shared__ int snd_sh[128], rcv_sh[128];
    __shared__ float sb0[128], sb1[128];

    const int tid = threadIdx.x, lane = tid & 31, warp = tid >> 5;
    const int row0 = blockIdx.x * 128;
    const int mr = (warp & 3) * 32, nc = (warp >> 2) * 64;
    const int g4 = lane >> 2, t4 = lane & 3;

    if (tid < 128) {
        sb0[tid] = b0[tid];
        if (MODE == 1) snd_sh[tid] = (row0 + tid < nrows) ? snd[row0 + tid] : 0;
    } else {
        int j = tid - 128;
        if (MODE == 3) { if (j < 3) sb1[j] = b1[j]; }
        else sb1[j] = b1[j];
        if (MODE == 1) rcv_sh[j] = (row0 + j < nrows) ? rcv[row0 + j] : 0;
    }
    float gg0 = 0.f, gg1 = 0.f;
    if (MODE == 1 || MODE == 2) { gg0 = glob[0]; gg1 = glob[1]; }
    __syncthreads();

    // ================= GEMM1: A[128 x 64*NC] @ W0 =================
    float acc[2][8][4];
#pragma unroll
    for (int mf = 0; mf < 2; mf++)
#pragma unroll
        for (int nf = 0; nf < 8; nf++)
#pragma unroll
            for (int q = 0; q < 4; q++) acc[mf][nf][q] = 0.f;

#pragma unroll 1
    for (int c = 0; c < NC; c++) {
        // gather A chunk -> hi/lo bf16 smem [128][72]
#pragma unroll
        for (int it = 0; it < 8; it++) {
            int i = tid + it * NT;
            int r = i >> 4, qi = i & 15;
            int row = row0 + r, k0 = c * 64 + qi * 4;
            float4 v = make_float4(0.f, 0.f, 0.f, 0.f);
            if (row < nrows) {
                if (MODE == 0) {
                    float vv[4];
#pragma unroll
                    for (int j = 0; j < 4; j++) vv[j] = (k0 + j < KIN) ? in0[(size_t)row * KIN + k0 + j] : 0.f;
                    v = make_float4(vv[0], vv[1], vv[2], vv[3]);
                } else if (MODE == 1) {
                    if (k0 < 128)       v = *(const float4*)(ehp + (size_t)row * 128 + k0);
                    else if (k0 < 256)  v = *(const float4*)(nhp + (size_t)snd_sh[r] * 128 + (k0 - 128));
                    else if (k0 < 384)  v = *(const float4*)(nhp + (size_t)rcv_sh[r] * 128 + (k0 - 256));
                    else if (k0 == 384) v = make_float4(gg0, gg1, 0.f, 0.f);
                } else if (MODE == 2) {
                    if (k0 < 128)       v = *(const float4*)(nhp + (size_t)row * 128 + k0);
                    else if (k0 < 256)  v = *(const float4*)(rca + (size_t)row * 128 + (k0 - 128));
                    else if (k0 == 256) v = make_float4(gg0, gg1, 0.f, 0.f);
                } else {
                    v = *(const float4*)(nhp + (size_t)row * 128 + k0);
                }
            }
            uint32_t h0 = packh(v.x, v.y), h1 = packh(v.z, v.w);
            uint32_t l0 = packl(v.x, v.y, h0), l1 = packl(v.z, v.w, h1);
            uint2 hv = make_uint2(h0, h1), lv = make_uint2(l0, l1);
            *(uint2*)((char*)sAh + r * 144 + qi * 8) = hv;
            *(uint2*)((char*)sAl + r * 144 + qi * 8) = lv;
        }
        // stage W0 chunk [128 n][64 k]
        for (int i = tid; i < 1024; i += NT) {
            int n = i >> 3, j = i & 7;
            *(uint4*)((char*)sBh + n * 144 + j * 16) = *(const uint4*)(g_whi + w0off + n * (NC * 64) + c * 64 + j * 8);
            *(uint4*)((char*)sBl + n * 144 + j * 16) = *(const uint4*)(g_wlo + w0off + n * (NC * 64) + c * 64 + j * 8);
        }
        __syncthreads();

        const uint32_t* Ahw = (const uint32_t*)sAh;
        const uint32_t* Alw = (const uint32_t*)sAl;
        const uint32_t* Bhw = (const uint32_t*)sBh;
        const uint32_t* Blw = (const uint32_t*)sBl;
#pragma unroll
        for (int ks = 0; ks < 4; ks++) {
            int kw = ks * 8 + t4;
            uint32_t ah[2][4], al[2][4], bh[8][2], bl[8][2];
#pragma unroll
            for (int mf = 0; mf < 2; mf++) {
                int rb = (mr + mf * 16 + g4) * 36;
                ah[mf][0] = Ahw[rb + kw];          ah[mf][1] = Ahw[rb + 288 + kw];
                ah[mf][2] = Ahw[rb + kw + 4];      ah[mf][3] = Ahw[rb + 288 + kw + 4];
                al[mf][0] = Alw[rb + kw];          al[mf][1] = Alw[rb + 288 + kw];
                al[mf][2] = Alw[rb + kw + 4];      al[mf][3] = Alw[rb + 288 + kw + 4];
            }
#pragma unroll
            for (int nf = 0; nf < 8; nf++) {
                int nb = (nc + nf * 8 + g4) * 36;
                bh[nf][0] = Bhw[nb + kw]; bh[nf][1] = Bhw[nb + kw + 4];
                bl[nf][0] = Blw[nb + kw]; bl[nf][1] = Blw[nb + kw + 4];
            }
#pragma unroll
            for (int mf = 0; mf < 2; mf++)
#pragma unroll
                for (int nf = 0; nf < 8; nf++) {
                    mmabf(acc[mf][nf], ah[mf], bh[nf]);
                    mmabf(acc[mf][nf], ah[mf], bl[nf]);
                    mmabf(acc[mf][nf], al[mf], bh[nf]);
                }
        }
        __syncthreads();
    }

    // ================= epilogue 1: bias + gelu =================
    if (MODE == 3) {
#pragma unroll
        for (int mf = 0; mf < 2; mf++)
#pragma unroll
            for (int nf = 0; nf < 8; nf++) {
                int r0 = mr + mf * 16 + g4, c0 = nc + nf * 8 + 2 * t4;
                sD[r0 * 132 + c0]       = gelu_f(acc[mf][nf][0] + sb0[c0]);
                sD[r0 * 132 + c0 + 1]   = gelu_f(acc[mf][nf][1] + sb0[c0 + 1]);
                sD[(r0 + 8) * 132 + c0]     = gelu_f(acc[mf][nf][2] + sb0[c0]);
                sD[(r0 + 8) * 132 + c0 + 1] = gelu_f(acc[mf][nf][3] + sb0[c0 + 1]);
            }
        __syncthreads();
        for (int i = tid; i < 128 * 3; i += NT) {
            int r = i / 3, cc = i - r * 3;
            int row = row0 + r;
            if (row < nrows) {
                float s = sb1[cc];
                const float* hr = sD + r * 132;
#pragma unroll 4
                for (int k = 0; k < 128; k++) s += hr[k] * __ldg(in0 + k * 3 + cc);
                outp[(size_t)row * 3 + cc] = s;
            }
        }
        return;
    }

    uint32_t* A2hw = (uint32_t*)sA2h;
    uint32_t* A2lw = (uint32_t*)sA2l;
#pragma unroll
    for (int mf = 0; mf < 2; mf++)
#pragma unroll
        for (int nf = 0; nf < 8; nf++) {
            int r0 = mr + mf * 16 + g4, c0 = nc + nf * 8 + 2 * t4;
            float v0 = gelu_f(acc[mf][nf][0] + sb0[c0]);
            float v1 = gelu_f(acc[mf][nf][1] + sb0[c0 + 1]);
            float v2 = gelu_f(acc[mf][nf][2] + sb0[c0]);
            float v3 = gelu_f(acc[mf][nf][3] + sb0[c0 + 1]);
            uint32_t h0 = packh(v0, v1), l0 = packl(v0, v1, h0);
            uint32_t h1 = packh(v2, v3), l1 = packl(v2, v3, h1);
            A2hw[r0 * 68 + (c0 >> 1)] = h0;  A2lw[r0 * 68 + (c0 >> 1)] = l0;
            A2hw[(r0 + 8) * 68 + (c0 >> 1)] = h1;  A2lw[(r0 + 8) * 68 + (c0 >> 1)] = l1;
        }
    __syncthreads();

    // ================= GEMM2: hidden[128x128] @ W1 =================
    float ac2[2][8][4];
#pragma unroll
    for (int mf = 0; mf < 2; mf++)
#pragma unroll
        for (int nf = 0; nf < 8; nf++)
#pragma unroll
            for (int q = 0; q < 4; q++) ac2[mf][nf][q] = 0.f;

#pragma unroll 1
    for (int c = 0; c < 2; c++) {
        for (int i = tid; i < 1024; i += NT) {
            int n = i >> 3, j = i & 7;
            *(uint4*)((char*)sBh + n * 144 + j * 16) = *(const uint4*)(g_whi + w1off + n * 128 + c * 64 + j * 8);
            *(uint4*)((char*)sBl + n * 144 + j * 16) = *(const uint4*)(g_wlo + w1off + n * 128 + c * 64 + j * 8);
        }
        __syncthreads();
        const uint32_t* Bhw = (const uint32_t*)sBh;
        const uint32_t* Blw = (const uint32_t*)sBl;
#pragma unroll
        for (int ks = 0; ks < 4; ks++) {
            int kw = ks * 8 + t4;
            uint32_t ah[2][4], al[2][4], bh[8][2], bl[8][2];
#pragma unroll
            for (int mf = 0; mf < 2; mf++) {
                int rb = (mr + mf * 16 + g4) * 68 + c * 32;
                ah[mf][0] = A2hw[rb + kw];        ah[mf][1] = A2hw[rb + 544 + kw];
                ah[mf][2] = A2hw[rb + kw + 4];    ah[mf][3] = A2hw[rb + 544 + kw + 4];
                al[mf][0] = A2lw[rb + kw];        al[mf][1] = A2lw[rb + 544 + kw];
                al[mf][2] = A2lw[rb + kw + 4];    al[mf][3] = A2lw[rb + 544 + kw + 4];
            }
#pragma unroll
            for (int nf = 0; nf < 8; nf++) {
                int nb = (nc + nf * 8 + g4) * 36;
                bh[nf][0] = Bhw[nb + kw]; bh[nf][1] = Bhw[nb + kw + 4];
                bl[nf][0] = Blw[nb + kw]; bl[nf][1] = Blw[nb + kw + 4];
            }
#pragma unroll
            for (int mf = 0; mf < 2; mf++)
#pragma unroll
                for (int nf = 0; nf < 8; nf++) {
                    mmabf(ac2[mf][nf], ah[mf], bh[nf]);
                    mmabf(ac2[mf][nf], ah[mf], bl[nf]);
                    mmabf(ac2[mf][nf], al[mf], bh[nf]);
                }
        }
        __syncthreads();
    }

    // ================= epilogue 2 =================
#pragma unroll
    for (int mf = 0; mf < 2; mf++)
#pragma unroll
        for (int nf = 0; nf < 8; nf++) {
            int r0 = mr + mf * 16 + g4, c0 = nc + nf * 8 + 2 * t4;
            sD[r0 * 132 + c0]       = ac2[mf][nf][0] + sb1[c0];
            sD[r0 * 132 + c0 + 1]   = ac2[mf][nf][1] + sb1[c0 + 1];
            sD[(r0 + 8) * 132 + c0]     = ac2[mf][nf][2] + sb1[c0];
            sD[(r0 + 8) * 132 + c0 + 1] = ac2[mf][nf][3] + sb1[c0 + 1];
        }
    __syncthreads();

    if (MODE == 0) {
        for (int i = tid; i < 128 * 32; i += NT) {
            int r = i >> 5, q = i & 31;
            int row = row0 + r;
            if (row < nrows) *(float4*)(outp + (size_t)row * 128 + q * 4) = *(float4*)(sD + r * 132 + q * 4);
        }
        return;
    }

    if (MODE == 1) {
        for (int i = tid; i < 128 * 32; i += NT) {
            int r = i >> 5, q = i & 31;
            int row = row0 + r;
            if (row < nrows) {
                float4 v = *(float4*)(sD + r * 132 + q * 4);
                float* dst = rca + (size_t)rcv_sh[r] * 128 + q * 4;
                atomicAdd(dst + 0, v.x); atomicAdd(dst + 1, v.y);
                atomicAdd(dst + 2, v.z); atomicAdd(dst + 3, v.w);
            }
        }
    }
    if (write_ln) {
        float4 sc = *(const float4*)(lnsc + lane * 4);
        float4 bsv = *(const float4*)(lnbs + lane * 4);
        const float* skp = (MODE == 1) ? ehp : nhp;
        for (int r = warp; r < 128; r += 8) {
            int row = row0 + r;
            float4 x = *(float4*)(sD + r * 132 + lane * 4);
            if (row < nrows) {
                float4 sk = *(const float4*)(skp + (size_t)row * 128 + lane * 4);
                x.x += sk.x; x.y += sk.y; x.z += sk.z; x.w += sk.w;
            }
            float s = wred(x.x + x.y + x.z + x.w);
            float mean = s * (1.f / 128.f);
            float dx = x.x - mean, dy = x.y - mean, dz = x.z - mean, dw = x.w - mean;
            float vv = wred(dx * dx + dy * dy + dz * dz + dw * dw);
            float inv = rsqrtf(vv * (1.f / 128.f) + 1e-6f);
            if (row < nrows) {
                float4 o;
                o.x = dx * inv * sc.x + bsv.x; o.y = dy * inv * sc.y + bsv.y;
                o.z = dz * inv * sc.z + bsv.z; o.w = dw * inv * sc.w + bsv.w;
                *(float4*)(outp + (size_t)row * 128 + lane * 4) = o;
            }
        }
    }
}

extern "C" void kernel_launch(void* const* d_in, const int* in_sizes, int n_in,
                              void* d_out, int out_size)
{
    const float* nodes  = (const float*)d_in[0];
    const float* edges  = (const float*)d_in[1];
    const float* glob   = (const float*)d_in[2];
    const int*   snd    = (const int*)d_in[3];
    const int*   rcv    = (const int*)d_in[4];
    const float* ne_W0  = (const float*)d_in[5];
    const float* ne_b0  = (const float*)d_in[6];
    const float* ne_W1  = (const float*)d_in[7];
    const float* ne_b1  = (const float*)d_in[8];
    const float* ee_W0  = (const float*)d_in[9];
    const float* ee_b0  = (const float*)d_in[10];
    const float* ee_W1  = (const float*)d_in[11];
    const float* ee_b1  = (const float*)d_in[12];
    const float* eu_W0  = (const float*)d_in[13];
    const float* eu_b0  = (const float*)d_in[14];
    const float* eu_W1  = (const float*)d_in[15];
    const float* eu_b1  = (const float*)d_in[16];
    const float* nu_W0  = (const float*)d_in[17];
    const float* nu_b0  = (const float*)d_in[18];
    const float* nu_W1  = (const float*)d_in[19];
    const float* nu_b1  = (const float*)d_in[20];
    const float* lnsc   = (const float*)d_in[21];
    const float* lnbs   = (const float*)d_in[22];
    const float* dec_W0 = (const float*)d_in[23];
    const float* dec_b0 = (const float*)d_in[24];
    const float* dec_W1 = (const float*)d_in[25];
    const float* dec_b1 = (const float*)d_in[26];
    float* out = (float*)d_out;

    const int N = in_sizes[0] / 7;
    const int E = in_sizes[1] / 3;

    float *nh, *eh, *rc;
    cudaGetSymbolAddress((void**)&nh, g_nh);
    cudaGetSymbolAddress((void**)&eh, g_eh);
    cudaGetSymbolAddress((void**)&rc, g_rc);

    // elem offsets into g_whi/g_wlo ([n][Kpad] layout)
    const int O_NEW0 = 0;            // Kpad 64
    const int O_NEW1 = 8192;         // 128
    const int O_EEW0 = 24576;        // 64
    const int O_EEW1 = 32768;        // 128
    const int O_EUW0_0 = 49152;      // 448
    const int O_EUW1_0 = 106496;     // 128
    const int O_EUW0_1 = 122880;     // 448
    const int O_EUW1_1 = 180224;     // 128
    const int O_NUW0_0 = 196608;     // 320
    const int O_NUW1_0 = 237568;     // 128
    const int O_NUW0_1 = 253952;     // 320
    const int O_NUW1_1 = 294912;     // 128
    const int O_DEC0 = 311296;       // 128

    prep<<<32, NT>>>(ne_W0, 7, 64, O_NEW0);
    prep<<<64, NT>>>(ne_W1, 128, 128, O_NEW1);
    prep<<<32, NT>>>(ee_W0, 3, 64, O_EEW0);
    prep<<<64, NT>>>(ee_W1, 128, 128, O_EEW1);
    prep<<<224, NT>>>(eu_W0, 386, 448, O_EUW0_0);
    prep<<<64, NT>>>(eu_W1, 128, 128, O_EUW1_0);
    prep<<<224, NT>>>(eu_W0 + (size_t)386 * 128, 386, 448, O_EUW0_1);
    prep<<<64, NT>>>(eu_W1 + (size_t)128 * 128, 128, 128, O_EUW1_1);
    prep<<<160, NT>>>(nu_W0, 258, 320, O_NUW0_0);
    prep<<<64, NT>>>(nu_W1, 128, 128, O_NUW1_0);
    prep<<<160, NT>>>(nu_W0 + (size_t)258 * 128, 258, 320, O_NUW0_1);
    prep<<<64, NT>>>(nu_W1 + (size_t)128 * 128, 128, 128, O_NUW1_1);
    prep<<<64, NT>>>(dec_W0, 128, 128, O_DEC0);

    cudaFuncSetAttribute(gk<0, 1, 7>,   cudaFuncAttributeMaxDynamicSharedMemorySize, SMEMSZ);
    cudaFuncSetAttribute(gk<0, 1, 3>,   cudaFuncAttributeMaxDynamicSharedMemorySize, SMEMSZ);
    cudaFuncSetAttribute(gk<1, 7, 386>, cudaFuncAttributeMaxDynamicSharedMemorySize, SMEMSZ);
    cudaFuncSetAttribute(gk<2, 5, 258>, cudaFuncAttributeMaxDynamicSharedMemorySize, SMEMSZ);
    cudaFuncSetAttribute(gk<3, 2, 128>, cudaFuncAttributeMaxDynamicSharedMemorySize, SMEMSZ);

    const int nbN = (N + 127) / 128;
    const int nbE = (E + 127) / 128;

    gk<0, 1, 7><<<nbN, NT, SMEMSZ>>>(N, nodes, O_NEW0, O_NEW1, ne_b0, ne_b1, nh,
        nullptr, nullptr, nullptr, nullptr, nullptr, nullptr, nullptr, nullptr, 0);
    gk<0, 1, 3><<<nbE, NT, SMEMSZ>>>(E, edges, O_EEW0, O_EEW1, ee_b0, ee_b1, eh,
        nullptr, nullptr, nullptr, nullptr, nullptr, nullptr, nullptr, nullptr, 0);

    for (int s = 0; s < 2; s++) {
        zerok<<<(N * 32 + 255) / 256, 256>>>((float4*)rc, N * 32);
        gk<1, 7, 386><<<nbE, NT, SMEMSZ>>>(E, nullptr,
            s ? O_EUW0_1 : O_EUW0_0, s ? O_EUW1_1 : O_EUW1_0,
            eu_b0 + s * 128, eu_b1 + s * 128, eh,
            snd, rcv, nh, eh, glob, rc, lnsc, lnbs, (s == 0) ? 1 : 0);
        gk<2, 5, 258><<<nbN, NT, SMEMSZ>>>(N, nullptr,
            s ? O_NUW0_1 : O_NUW0_0, s ? O_NUW1_1 : O_NUW1_0,
            nu_b0 + s * 128, nu_b1 + s * 128, nh,
            nullptr, nullptr, nh, nullptr, glob, rc, lnsc, lnbs, 1);
    }

    gk<3, 2, 128><<<nbN, NT, SMEMSZ>>>(N, dec_W1, O_DEC0, 0, dec_b0, dec_b1, out,
        nullptr, nullptr, nh, nullptr, nullptr, nullptr, nullptr, nullptr, 0);
}